// round 1
// baseline (speedup 1.0000x reference)
#include <cuda_runtime.h>
#include <math.h>

// Problem constants: B=32, N=1024, DIM=768, GP=49
// inputs: x[32,1024,768], w_qkv[768,2304], b_qkv[2304], w_proj[768,768], b_proj[768], w_gp[768,49]
// output: [32,1024,768] fp32

// ---------------- scratch (static device globals; no allocation allowed) ----------
__device__ float g_qkv[(size_t)32768 * 2304];      // 288 MB : q|k|v interleaved rows, ld=2304
__device__ float g_S  [(size_t)32 * 1024 * 1024];  // 128 MB : scores, then attn in-place
__device__ float g_G  [(size_t)32 * 1024 * 1024];  // 128 MB : gw @ gw^T
__device__ float g_gw [(size_t)32768 * 49];        // 6.4 MB : softmax(v @ w_gp)
__device__ float g_av [(size_t)32768 * 768];       // 96 MB  : attn @ V
__device__ float g_wgpT[49 * 768];                 // transposed w_gp

// ---------------- generic fp32 tiled GEMM: C = scale*(A@B[^T]) (+bias) ------------
// Block tile 128x128, K-tile 8, 256 threads, 8x8 per-thread micro-tile.
// A row-major [M,K]; B row-major [K,N] (NN) or [N,K] (NT). All tile dims assumed
// to divide M,N; K divisible by 8 (true for every call below).
template<bool TRANSB, bool BIAS>
__global__ void __launch_bounds__(256) sgemm128(
    const float* __restrict__ A, const float* __restrict__ B,
    const float* __restrict__ bias, float* __restrict__ C,
    int K, int lda, int ldb, int ldc,
    long long sA, long long sB, long long sC, float scale)
{
    const int m0 = blockIdx.y * 128;
    const int n0 = blockIdx.x * 128;
    A += (long long)blockIdx.z * sA;
    B += (long long)blockIdx.z * sB;
    C += (long long)blockIdx.z * sC;

    __shared__ __align__(16) float As[8][128];
    __shared__ __align__(16) float Bs[8][128];

    const int tid = threadIdx.x;
    const int tx  = tid & 15;
    const int ty  = tid >> 4;

    // load indexing
    const int arow = tid >> 1;        // 0..127
    const int akq  = (tid & 1) * 4;   // 0 or 4
    const float* Aload = A + (long long)(m0 + arow) * lda + akq;

    const int brow = tid >> 5;        // 0..7   (NN path)
    const int bcol = (tid & 31) * 4;  // 0..124 (NN path)
    const float* Bload = TRANSB
        ? (B + (long long)(n0 + arow) * ldb + akq)
        : (B + (long long)brow * ldb + n0 + bcol);

    float acc[8][8];
    #pragma unroll
    for (int i = 0; i < 8; i++)
        #pragma unroll
        for (int j = 0; j < 8; j++) acc[i][j] = 0.0f;

    for (int k0 = 0; k0 < K; k0 += 8) {
        float4 av = *(const float4*)(Aload + k0);
        As[akq + 0][arow] = av.x;
        As[akq + 1][arow] = av.y;
        As[akq + 2][arow] = av.z;
        As[akq + 3][arow] = av.w;
        if (TRANSB) {
            float4 bv = *(const float4*)(Bload + k0);
            Bs[akq + 0][arow] = bv.x;
            Bs[akq + 1][arow] = bv.y;
            Bs[akq + 2][arow] = bv.z;
            Bs[akq + 3][arow] = bv.w;
        } else {
            float4 bv = *(const float4*)(Bload + (long long)k0 * ldb);
            *(float4*)&Bs[brow][bcol] = bv;
        }
        __syncthreads();
        #pragma unroll
        for (int kk = 0; kk < 8; kk++) {
            float a[8], b[8];
            *(float4*)(a)     = *(const float4*)&As[kk][ty * 4];
            *(float4*)(a + 4) = *(const float4*)&As[kk][64 + ty * 4];
            *(float4*)(b)     = *(const float4*)&Bs[kk][tx * 4];
            *(float4*)(b + 4) = *(const float4*)&Bs[kk][64 + tx * 4];
            #pragma unroll
            for (int i = 0; i < 8; i++)
                #pragma unroll
                for (int j = 0; j < 8; j++)
                    acc[i][j] = fmaf(a[i], b[j], acc[i][j]);
        }
        __syncthreads();
    }

    #pragma unroll
    for (int i = 0; i < 8; i++) {
        const int row = m0 + ((i < 4) ? (ty * 4 + i) : (64 + ty * 4 + (i - 4)));
        #pragma unroll
        for (int jh = 0; jh < 2; jh++) {
            const int col = n0 + jh * 64 + tx * 4;
            float4 o;
            o.x = acc[i][jh * 4 + 0] * scale;
            o.y = acc[i][jh * 4 + 1] * scale;
            o.z = acc[i][jh * 4 + 2] * scale;
            o.w = acc[i][jh * 4 + 3] * scale;
            if (BIAS) {
                o.x += bias[col + 0];
                o.y += bias[col + 1];
                o.z += bias[col + 2];
                o.w += bias[col + 3];
            }
            *(float4*)&C[(long long)row * ldc + col] = o;
        }
    }
}

// ---------------- transpose w_gp [768,49] -> wgpT [49,768] ------------------------
__global__ void transpose_wgp(const float* __restrict__ w_gp, float* __restrict__ wgpT)
{
    int i = blockIdx.x * 256 + threadIdx.x;
    if (i < 768 * 49) {
        int d = i / 49, g = i % 49;
        wgpT[g * 768 + d] = w_gp[i];
    }
}

// ---------------- gw = softmax(V @ w_gp) row-wise ---------------------------------
// one block per row (32768 rows), 256 threads
__global__ void __launch_bounds__(256) gw_kernel(
    const float* __restrict__ qkv, const float* __restrict__ wgpT,
    float* __restrict__ gw)
{
    __shared__ __align__(16) float vs[768];
    __shared__ float dots[49];
    __shared__ float sinv;

    const long long row = blockIdx.x;
    const float* v = qkv + row * 2304 + 1536;
    const int tid = threadIdx.x;

    if (tid < 192) ((float4*)vs)[tid] = ((const float4*)v)[tid];
    __syncthreads();

    const int warp = tid >> 5;
    const int lane = tid & 31;
    for (int g = warp; g < 49; g += 8) {
        const float* wg = wgpT + g * 768;
        float acc = 0.0f;
        #pragma unroll 4
        for (int d = lane; d < 768; d += 32) acc = fmaf(vs[d], wg[d], acc);
        #pragma unroll
        for (int o = 16; o; o >>= 1) acc += __shfl_xor_sync(0xffffffffu, acc, o);
        if (lane == 0) dots[g] = acc;
    }
    __syncthreads();

    if (tid == 0) {
        float m = dots[0];
        #pragma unroll
        for (int i = 1; i < 49; i++) m = fmaxf(m, dots[i]);
        float sum = 0.0f;
        for (int i = 0; i < 49; i++) { float e = __expf(dots[i] - m); dots[i] = e; sum += e; }
        sinv = 1.0f / sum;
    }
    __syncthreads();
    if (tid < 49) gw[row * 49 + tid] = dots[tid] * sinv;
}

// ---------------- G = gw @ gw^T (batched, K=49) ------------------------------------
// 64x64 tile per block, 256 threads, 4x4 per thread
__global__ void __launch_bounds__(256) gmat_kernel(
    const float* __restrict__ gw, float* __restrict__ G)
{
    __shared__ __align__(16) float Sq[49][64];
    __shared__ __align__(16) float Sk[49][64];

    const int b  = blockIdx.z;
    const int q0 = blockIdx.y * 64;
    const int k0 = blockIdx.x * 64;
    const float* gwb = gw + (long long)b * 1024 * 49;
    const int tid = threadIdx.x;

    for (int i = tid; i < 64 * 49; i += 256) {
        int r = i / 49, c = i % 49;
        Sq[c][r] = gwb[(q0 + r) * 49 + c];
        Sk[c][r] = gwb[(k0 + r) * 49 + c];
    }
    __syncthreads();

    const int tx = tid & 15, ty = tid >> 4;
    float acc[4][4];
    #pragma unroll
    for (int i = 0; i < 4; i++)
        #pragma unroll
        for (int j = 0; j < 4; j++) acc[i][j] = 0.0f;

    for (int g = 0; g < 49; g++) {
        float4 aq = *(const float4*)&Sq[g][ty * 4];
        float4 bk = *(const float4*)&Sk[g][tx * 4];
        float a[4] = {aq.x, aq.y, aq.z, aq.w};
        float c[4] = {bk.x, bk.y, bk.z, bk.w};
        #pragma unroll
        for (int i = 0; i < 4; i++)
            #pragma unroll
            for (int j = 0; j < 4; j++)
                acc[i][j] = fmaf(a[i], c[j], acc[i][j]);
    }

    float* Gb = G + (long long)b * 1024 * 1024;
    #pragma unroll
    for (int i = 0; i < 4; i++) {
        float4 o = {acc[i][0], acc[i][1], acc[i][2], acc[i][3]};
        *(float4*)&Gb[(long long)(q0 + ty * 4 + i) * 1024 + k0 + tx * 4] = o;
    }
}

// ---------------- fused softmax*G normalize (in-place on S) ------------------------
// attn[q,k] = exp(s-m)*G / (sum_k exp(s-m)*G + eps) ; one block per row
__global__ void __launch_bounds__(256) attn_norm_kernel(
    float* __restrict__ S, const float* __restrict__ G)
{
    __shared__ float red[8];
    const long long row = blockIdx.x;
    float* s = S + row * 1024;
    const float* g = G + row * 1024;
    const int tid = threadIdx.x;

    float4 sv = ((const float4*)s)[tid];
    float m = fmaxf(fmaxf(sv.x, sv.y), fmaxf(sv.z, sv.w));
    #pragma unroll
    for (int o = 16; o; o >>= 1) m = fmaxf(m, __shfl_xor_sync(0xffffffffu, m, o));
    if ((tid & 31) == 0) red[tid >> 5] = m;
    __syncthreads();
    m = red[0];
    #pragma unroll
    for (int i = 1; i < 8; i++) m = fmaxf(m, red[i]);

    float4 gv = ((const float4*)g)[tid];
    float4 w;
    w.x = __expf(sv.x - m) * gv.x;
    w.y = __expf(sv.y - m) * gv.y;
    w.z = __expf(sv.z - m) * gv.z;
    w.w = __expf(sv.w - m) * gv.w;

    float ssum = w.x + w.y + w.z + w.w;
    #pragma unroll
    for (int o = 16; o; o >>= 1) ssum += __shfl_xor_sync(0xffffffffu, ssum, o);
    __syncthreads();                 // everyone done reading red (max phase)
    if ((tid & 31) == 0) red[tid >> 5] = ssum;
    __syncthreads();
    float tot = 0.0f;
    #pragma unroll
    for (int i = 0; i < 8; i++) tot += red[i];

    const float inv = 1.0f / (tot + 1e-8f);
    w.x *= inv; w.y *= inv; w.z *= inv; w.w *= inv;
    ((float4*)s)[tid] = w;
}

// ---------------- launch ------------------------------------------------------------
extern "C" void kernel_launch(void* const* d_in, const int* in_sizes, int n_in,
                              void* d_out, int out_size)
{
    const float* x      = (const float*)d_in[0];
    const float* w_qkv  = (const float*)d_in[1];
    const float* b_qkv  = (const float*)d_in[2];
    const float* w_proj = (const float*)d_in[3];
    const float* b_proj = (const float*)d_in[4];
    const float* w_gp   = (const float*)d_in[5];
    float* out = (float*)d_out;

    float *qkv, *S, *G, *gw, *av, *wgpT;
    cudaGetSymbolAddress((void**)&qkv,  g_qkv);
    cudaGetSymbolAddress((void**)&S,    g_S);
    cudaGetSymbolAddress((void**)&G,    g_G);
    cudaGetSymbolAddress((void**)&gw,   g_gw);
    cudaGetSymbolAddress((void**)&av,   g_av);
    cudaGetSymbolAddress((void**)&wgpT, g_wgpT);

    const float scaleS = 1.0f / sqrtf(768.0f);

    // 0. transpose w_gp for coalesced group dots
    transpose_wgp<<<(768 * 49 + 255) / 256, 256>>>(w_gp, wgpT);

    // 1. qkv = x @ w_qkv + b_qkv     [32768 x 2304], K=768
    sgemm128<false, true><<<dim3(18, 256, 1), 256>>>(
        x, w_qkv, b_qkv, qkv, 768, 768, 2304, 2304, 0, 0, 0, 1.0f);

    // 2. gw = softmax(V @ w_gp)
    gw_kernel<<<32768, 256>>>(qkv, wgpT, gw);

    // 3. S = (Q @ K^T) * scale      batched [1024 x 1024], K=768
    sgemm128<true, false><<<dim3(8, 8, 32), 256>>>(
        qkv, qkv + 768, nullptr, S, 768, 2304, 2304, 1024,
        1024LL * 2304, 1024LL * 2304, 1024LL * 1024, scaleS);

    // 4. G = gw @ gw^T              batched [1024 x 1024], K=49
    gmat_kernel<<<dim3(16, 16, 32), 256>>>(gw, G);

    // 5. attn = exp(S-m)*G / (rowsum + eps)   (in-place on S)
    attn_norm_kernel<<<32768, 256>>>(S, G);

    // 6. av = attn @ V              batched [1024 x 768], K=1024
    sgemm128<false, false><<<dim3(6, 8, 32), 256>>>(
        S, qkv + 1536, nullptr, av, 1024, 1024, 2304, 768,
        1024LL * 1024, 1024LL * 2304, 1024LL * 768, 1.0f);

    // 7. out = av @ w_proj + b_proj [32768 x 768], K=768
    sgemm128<false, true><<<dim3(6, 256, 1), 256>>>(
        av, w_proj, b_proj, out, 768, 768, 768, 768, 0, 0, 0, 1.0f);
}

// round 3
// speedup vs baseline: 3.8041x; 3.8041x over previous
#include <cuda_runtime.h>
#include <math.h>
#include <stdint.h>

// B=32, N=1024, DIM=768, GP=49
// ---------------- scratch ----------------
__device__ float g_qkv [(size_t)32768 * 2304];     // q|k|v rows, ld=2304 (tf32-rounded)
__device__ float g_S   [(size_t)32 * 1024 * 1024]; // scores -> attn (attn tf32-rounded)
__device__ float g_G   [(size_t)32 * 1024 * 1024];
__device__ float g_gw  [(size_t)32768 * 64];       // softmax groups, K padded to 64, rounded
__device__ float g_dots[(size_t)32768 * 128];      // V@w_gp, N padded to 128
__device__ float g_av  [(size_t)32768 * 768];      // attn@V (rounded)
__device__ float g_vt  [(size_t)32 * 768 * 1024];  // V^T (rounded)
__device__ float g_x   [(size_t)32768 * 768];      // x rounded to tf32
__device__ float g_wqkvT[(size_t)2304 * 768];      // rounded
__device__ float g_wprojT[(size_t)768 * 768];      // rounded
__device__ float g_wgpT [(size_t)128 * 768];       // rows 49..127 zero, rounded

// ---------------- helpers ----------------
static __device__ __forceinline__ float rtf(float f) {
    uint32_t r; asm("cvt.rna.tf32.f32 %0, %1;" : "=r"(r) : "f"(f));
    return __uint_as_float(r);
}
static __device__ __forceinline__ uint32_t s2u(const void* p) {
    uint32_t a;
    asm("{ .reg .u64 t; cvta.to.shared.u64 t, %1; cvt.u32.u64 %0, t; }" : "=r"(a) : "l"(p));
    return a;
}
#define CPA16(dst, src) \
    asm volatile("cp.async.cg.shared.global [%0], [%1], 16;" :: "r"(dst), "l"(src) : "memory")
#define CPA_COMMIT() asm volatile("cp.async.commit_group;" ::: "memory")

// ================= tf32 mma.sync GEMM =================
// C[M,N] = scale*(A[M,K] @ B[N,K]^T) (+bias[N]), optional tf32-rounding of output.
// A,B row-major K-major, tf32-pre-rounded. M,N mult of 128; K mult of 32.
// 256 threads, 128x128 block tile, warp grid 2(m) x 4(n), K-tile 32, cp.async 2-stage.
__global__ void __launch_bounds__(256) tgemm(
    const float* __restrict__ A, const float* __restrict__ B,
    const float* __restrict__ bias, float* __restrict__ C,
    int K, int lda, int ldb, int ldc,
    long long sA, long long sB, long long sC, float scale, int roundOut)
{
    extern __shared__ __align__(16) float sm[];   // [A0 4096][B0 4096][A1][B1] floats
    const uint32_t sbase = s2u(sm);

    const int tid = threadIdx.x;
    const int lane = tid & 31, wid = tid >> 5;
    const int wm = wid & 1, wn = wid >> 1;
    const int r4 = lane >> 2, q = lane & 3;
    const int m0 = blockIdx.y * 128, n0 = blockIdx.x * 128;

    A += (long long)blockIdx.z * sA + (long long)m0 * lda;
    B += (long long)blockIdx.z * sB + (long long)n0 * ldb;
    C += (long long)blockIdx.z * sC;

    // per-thread cp.async offsets: 4 chunks of 16B each for A and B
    uint32_t swOff[4]; long long gA[4], gB[4];
    #pragma unroll
    for (int p = 0; p < 4; p++) {
        int idx = p * 256 + tid;
        int r = idx >> 3, c4 = idx & 7;
        swOff[p] = (uint32_t)(((r << 5) + ((c4 ^ (r & 7)) << 2)) << 2); // bytes
        gA[p] = (long long)r * lda + c4 * 4;
        gB[p] = (long long)r * ldb + c4 * 4;
    }

    const int nk = K / 32;

    // prologue: stage 0 into buffer 0
    #pragma unroll
    for (int p = 0; p < 4; p++) {
        CPA16(sbase + swOff[p],         A + gA[p]);
        CPA16(sbase + 16384 + swOff[p], B + gB[p]);
    }
    CPA_COMMIT();

    float acc[4][4][4];
    #pragma unroll
    for (int i = 0; i < 4; i++)
        #pragma unroll
        for (int j = 0; j < 4; j++)
            #pragma unroll
            for (int v = 0; v < 4; v++) acc[i][j][v] = 0.0f;

    for (int kt = 0; kt < nk; kt++) {
        const int buf = kt & 1;
        if (kt + 1 < nk) {
            const float* An = A + (kt + 1) * 32;
            const float* Bn = B + (kt + 1) * 32;
            const uint32_t db = sbase + (uint32_t)((buf ^ 1) * 32768);
            #pragma unroll
            for (int p = 0; p < 4; p++) {
                CPA16(db + swOff[p],         An + gA[p]);
                CPA16(db + 16384 + swOff[p], Bn + gB[p]);
            }
            CPA_COMMIT();
            asm volatile("cp.async.wait_group 1;" ::: "memory");
        } else {
            asm volatile("cp.async.wait_group 0;" ::: "memory");
        }
        __syncthreads();

        const float* As = sm + buf * 8192;
        const float* Bs = As + 4096;

        #pragma unroll
        for (int ks = 0; ks < 4; ks++) {
            const int c0 = (((2 * ks)     ^ r4) << 2) | q;  // k = ks*8 + q
            const int c1 = (((2 * ks + 1) ^ r4) << 2) | q;  // k = ks*8 + q + 4
            uint32_t a[4][4], b[4][2];
            #pragma unroll
            for (int mi = 0; mi < 4; mi++) {
                const int rb = (wm * 64 + mi * 16 + r4) << 5;
                a[mi][0] = __float_as_uint(As[rb + c0]);
                a[mi][1] = __float_as_uint(As[rb + 256 + c0]);   // row +8
                a[mi][2] = __float_as_uint(As[rb + c1]);
                a[mi][3] = __float_as_uint(As[rb + 256 + c1]);
            }
            #pragma unroll
            for (int ni = 0; ni < 4; ni++) {
                const int nb = (wn * 32 + ni * 8 + r4) << 5;
                b[ni][0] = __float_as_uint(Bs[nb + c0]);
                b[ni][1] = __float_as_uint(Bs[nb + c1]);
            }
            #pragma unroll
            for (int mi = 0; mi < 4; mi++)
                #pragma unroll
                for (int ni = 0; ni < 4; ni++)
                    asm volatile(
                        "mma.sync.aligned.m16n8k8.row.col.f32.tf32.tf32.f32 "
                        "{%0,%1,%2,%3}, {%4,%5,%6,%7}, {%8,%9}, {%0,%1,%2,%3};"
                        : "+f"(acc[mi][ni][0]), "+f"(acc[mi][ni][1]),
                          "+f"(acc[mi][ni][2]), "+f"(acc[mi][ni][3])
                        : "r"(a[mi][0]), "r"(a[mi][1]), "r"(a[mi][2]), "r"(a[mi][3]),
                          "r"(b[ni][0]), "r"(b[ni][1]));
        }
        __syncthreads();
    }

    // epilogue: c0 (r4, 2q) c1 (r4, 2q+1) c2 (r4+8, 2q) c3 (r4+8, 2q+1)
    #pragma unroll
    for (int ni = 0; ni < 4; ni++) {
        const int col = n0 + wn * 32 + ni * 8 + 2 * q;
        float bx = 0.0f, by = 0.0f;
        if (bias) { bx = bias[col]; by = bias[col + 1]; }
        #pragma unroll
        for (int mi = 0; mi < 4; mi++) {
            const int row = m0 + wm * 64 + mi * 16 + r4;
            float2 v0, v1;
            v0.x = acc[mi][ni][0] * scale + bx;
            v0.y = acc[mi][ni][1] * scale + by;
            v1.x = acc[mi][ni][2] * scale + bx;
            v1.y = acc[mi][ni][3] * scale + by;
            if (roundOut) {
                v0.x = rtf(v0.x); v0.y = rtf(v0.y);
                v1.x = rtf(v1.x); v1.y = rtf(v1.y);
            }
            *(float2*)&C[(long long)row * ldc + col] = v0;
            *(float2*)&C[(long long)(row + 8) * ldc + col] = v1;
        }
    }
}

// ================= aux kernels =================
__global__ void round_x(const float* __restrict__ src, float* __restrict__ dst)
{
    const long long i = (long long)blockIdx.x * 256 + threadIdx.x;
    float4 v = ((const float4*)src)[i];
    v.x = rtf(v.x); v.y = rtf(v.y); v.z = rtf(v.z); v.w = rtf(v.w);
    ((float4*)dst)[i] = v;
}

// tiled transpose with tf32 rounding: dst[c][r] = round(src[r][c])
__global__ void ttrans(const float* __restrict__ src, float* __restrict__ dst,
                       int lds, int ldd, long long ss, long long sd)
{
    __shared__ float t[32][33];
    src += (long long)blockIdx.z * ss;
    dst += (long long)blockIdx.z * sd;
    const int r0 = blockIdx.x * 32, c0 = blockIdx.y * 32;
    const int x = threadIdx.x, y = threadIdx.y;
    #pragma unroll
    for (int i = y; i < 32; i += 8)
        t[i][x] = src[(long long)(r0 + i) * lds + c0 + x];
    __syncthreads();
    #pragma unroll
    for (int i = y; i < 32; i += 8)
        dst[(long long)(c0 + i) * ldd + r0 + x] = rtf(t[x][i]);
}

__global__ void wgp_pad(const float* __restrict__ w_gp, float* __restrict__ wgpT)
{
    int i = blockIdx.x * 256 + threadIdx.x;
    if (i < 128 * 768) {
        int g = i / 768, d = i % 768;
        wgpT[i] = (g < 49) ? rtf(w_gp[d * 49 + g]) : 0.0f;
    }
}

// softmax over dots[:,0:49] -> gw [32768,64] (cols 49..63 zero), tf32-rounded
__global__ void __launch_bounds__(128) gw_softmax(const float* __restrict__ dots,
                                                  float* __restrict__ gw)
{
    const int row = blockIdx.x * 4 + (threadIdx.x >> 5);
    const int t = threadIdx.x & 31;
    const float* d = dots + (long long)row * 128;
    float a = d[t];
    float b = (t < 17) ? d[32 + t] : -1e30f;
    float m = fmaxf(a, b);
    #pragma unroll
    for (int o = 16; o; o >>= 1) m = fmaxf(m, __shfl_xor_sync(0xffffffffu, m, o));
    float ea = __expf(a - m);
    float eb = (t < 17) ? __expf(b - m) : 0.0f;
    float s = ea + eb;
    #pragma unroll
    for (int o = 16; o; o >>= 1) s += __shfl_xor_sync(0xffffffffu, s, o);
    const float inv = 1.0f / s;
    float* g = gw + (long long)row * 64;
    g[t] = rtf(ea * inv);
    g[32 + t] = rtf(eb * inv);
}

// attn = exp(S-m)*G / (rowsum+eps), in-place on S, tf32-rounded output
__global__ void __launch_bounds__(256) attn_norm(float* __restrict__ S, const float* __restrict__ G)
{
    __shared__ float red[8];
    const long long row = blockIdx.x;
    float* s = S + row * 1024;
    const float* g = G + row * 1024;
    const int tid = threadIdx.x;

    float4 sv = ((const float4*)s)[tid];
    float m = fmaxf(fmaxf(sv.x, sv.y), fmaxf(sv.z, sv.w));
    #pragma unroll
    for (int o = 16; o; o >>= 1) m = fmaxf(m, __shfl_xor_sync(0xffffffffu, m, o));
    if ((tid & 31) == 0) red[tid >> 5] = m;
    __syncthreads();
    m = red[0];
    #pragma unroll
    for (int i = 1; i < 8; i++) m = fmaxf(m, red[i]);

    float4 gv = ((const float4*)g)[tid];
    float4 w;
    w.x = __expf(sv.x - m) * gv.x;
    w.y = __expf(sv.y - m) * gv.y;
    w.z = __expf(sv.z - m) * gv.z;
    w.w = __expf(sv.w - m) * gv.w;

    float ssum = w.x + w.y + w.z + w.w;
    #pragma unroll
    for (int o = 16; o; o >>= 1) ssum += __shfl_xor_sync(0xffffffffu, ssum, o);
    __syncthreads();
    if ((tid & 31) == 0) red[tid >> 5] = ssum;
    __syncthreads();
    float tot = 0.0f;
    #pragma unroll
    for (int i = 0; i < 8; i++) tot += red[i];

    const float inv = 1.0f / (tot + 1e-8f);
    w.x = rtf(w.x * inv); w.y = rtf(w.y * inv);
    w.z = rtf(w.z * inv); w.w = rtf(w.w * inv);
    ((float4*)s)[tid] = w;
}

// ================= launch =================
extern "C" void kernel_launch(void* const* d_in, const int* in_sizes, int n_in,
                              void* d_out, int out_size)
{
    const float* x      = (const float*)d_in[0];
    const float* w_qkv  = (const float*)d_in[1];
    const float* b_qkv  = (const float*)d_in[2];
    const float* w_proj = (const float*)d_in[3];
    const float* b_proj = (const float*)d_in[4];
    const float* w_gp   = (const float*)d_in[5];
    float* out = (float*)d_out;

    float *qkv, *S, *G, *gw, *dots, *av, *vt, *xr, *wqkvT, *wprojT, *wgpT;
    cudaGetSymbolAddress((void**)&qkv, g_qkv);
    cudaGetSymbolAddress((void**)&S, g_S);
    cudaGetSymbolAddress((void**)&G, g_G);
    cudaGetSymbolAddress((void**)&gw, g_gw);
    cudaGetSymbolAddress((void**)&dots, g_dots);
    cudaGetSymbolAddress((void**)&av, g_av);
    cudaGetSymbolAddress((void**)&vt, g_vt);
    cudaGetSymbolAddress((void**)&xr, g_x);
    cudaGetSymbolAddress((void**)&wqkvT, g_wqkvT);
    cudaGetSymbolAddress((void**)&wprojT, g_wprojT);
    cudaGetSymbolAddress((void**)&wgpT, g_wgpT);

    const int SMEM = 65536;
    cudaFuncSetAttribute(tgemm, cudaFuncAttributeMaxDynamicSharedMemorySize, SMEM);

    const float scaleS = 1.0f / sqrtf(768.0f);
    dim3 tb(32, 8);

    // producers: round everything that feeds an MMA operand to tf32
    round_x<<<24576, 256>>>(x, xr);
    ttrans<<<dim3(24, 72, 1), tb>>>(w_qkv, wqkvT, 2304, 768, 0, 0);
    ttrans<<<dim3(24, 24, 1), tb>>>(w_proj, wprojT, 768, 768, 0, 0);
    wgp_pad<<<384, 256>>>(w_gp, wgpT);

    // qkv = x @ w_qkv + b   [32768,2304] K=768  (rounded)
    tgemm<<<dim3(18, 256, 1), 256, SMEM>>>(
        xr, wqkvT, b_qkv, qkv, 768, 768, 768, 2304, 0, 0, 0, 1.0f, 1);

    // vt = V^T per batch (rounded; V already rounded so no-op numerically)
    ttrans<<<dim3(32, 24, 32), tb>>>(qkv + 1536, vt, 2304, 1024, 1024LL * 2304, 768LL * 1024);

    // dots = V @ w_gp  (N padded 128)
    tgemm<<<dim3(1, 256, 1), 256, SMEM>>>(
        qkv + 1536, wgpT, nullptr, dots, 768, 2304, 768, 128, 0, 0, 0, 1.0f, 0);

    // S = Q @ K^T * scale  batched
    tgemm<<<dim3(8, 8, 32), 256, SMEM>>>(
        qkv, qkv + 768, nullptr, S, 768, 2304, 2304, 1024,
        1024LL * 2304, 1024LL * 2304, 1024LL * 1024, scaleS, 0);

    gw_softmax<<<8192, 128>>>(dots, gw);

    // G = gw @ gw^T  (K padded 64)
    tgemm<<<dim3(8, 8, 32), 256, SMEM>>>(
        gw, gw, nullptr, G, 64, 64, 64, 1024,
        1024LL * 64, 1024LL * 64, 1024LL * 1024, 1.0f, 0);

    attn_norm<<<32768, 256>>>(S, G);

    // av = attn @ V  (rounded)
    tgemm<<<dim3(6, 8, 32), 256, SMEM>>>(
        S, vt, nullptr, av, 1024, 1024, 1024, 768,
        1024LL * 1024, 768LL * 1024, 1024LL * 768, 1.0f, 1);

    // out = av @ w_proj + b  (final, not rounded)
    tgemm<<<dim3(6, 256, 1), 256, SMEM>>>(
        av, wprojT, b_proj, out, 768, 768, 768, 768, 0, 0, 0, 1.0f, 0);
}